// round 4
// baseline (speedup 1.0000x reference)
#include <cuda_runtime.h>
#include <math.h>

#define BATCH   64
#define IN_F    512
#define OUT_F   512

// Scratch (no allocations allowed -> __device__ globals)
__device__ float gW[OUT_F * IN_F];        // scaled, masked w
__device__ float gA[8 * 64 * 64];         // gA[d][i][o] = exp(g[d,o,i])

// ---------------------------------------------------------------------------
// K1: per-row weight prep. One block (128 thr) per row r of W.
// ---------------------------------------------------------------------------
__global__ void __launch_bounds__(128) k_weights(const float* __restrict__ W,
                                                 const float* __restrict__ diag_w) {
    const int r   = blockIdx.x;
    const int rb  = r >> 6;
    const int lo  = rb << 6;
    const int hi  = lo + 64;
    const int tid = threadIdx.x;

    const float4 wv4 = ((const float4*)(W + r * IN_F))[tid];
    float wv[4] = {wv4.x, wv4.y, wv4.z, wv4.w};
    float wu[4];
    float ss = 0.f;
    #pragma unroll
    for (int j = 0; j < 4; j++) {
        const int c = tid * 4 + j;
        float u;
        if (c >= hi)      u = 0.f;
        else if (c >= lo) u = __expf(wv[j]);
        else              u = wv[j];
        wu[j] = u;
        ss += u * u;
    }
    #pragma unroll
    for (int off = 16; off > 0; off >>= 1)
        ss += __shfl_down_sync(0xffffffffu, ss, off);
    __shared__ float sred[4];
    __shared__ float sbc[2];
    if ((tid & 31) == 0) sred[tid >> 5] = ss;
    __syncthreads();
    if (tid == 0) {
        const float wsn = sred[0] + sred[1] + sred[2] + sred[3];
        const float dv  = diag_w[r];
        sbc[0] = __expf(dv) * rsqrtf(wsn);       // row scale for w
        sbc[1] = dv - 0.5f * __logf(wsn);        // c1 for g
    }
    __syncthreads();
    const float scale = sbc[0];
    const float c1    = sbc[1];
    float4 o4 = make_float4(scale * wu[0], scale * wu[1], scale * wu[2], scale * wu[3]);
    ((float4*)(gW + r * IN_F))[tid] = o4;
    #pragma unroll
    for (int j = 0; j < 4; j++) {
        const int c = tid * 4 + j;
        if (c >= lo && c < hi) {
            const int i = c - lo;
            gA[(rb * 64 + i) * 64 + (r - lo)] = __expf(c1 + wv[j]);   // [d][i][o]
        }
    }
}

// ---------------------------------------------------------------------------
// K2 fused, 256 threads, 2 CTAs/SM:
//   bid <  256 : jac for TWO batches (b0,b1) sharing gA[d].  4o x 4k x 2b acc.
//   bid >= 256 : out tile (16b x 64r, full K=512, bias inline)
// ---------------------------------------------------------------------------
__global__ void __launch_bounds__(256, 2) k_main(
        const float* __restrict__ grad,
        const float* __restrict__ inputs,
        const float* __restrict__ bias,
        float* __restrict__ outp) {
    __shared__ float smemBuf[12288];     // 48 KB
    const int bid = blockIdx.x;
    const int tid = threadIdx.x;

    if (bid < 256) {
        // ---------------- jac: C = gA[d]^T @ exp(grad_b);  log ----------------
        const int d     = bid & 7;
        const int bpair = bid >> 3;            // 0..31
        const int jb0   = bpair * 16 + d;      // (2*bpair)  *8 + d
        const int jb1   = jb0 + 8;             // (2*bpair+1)*8 + d
        float* As  = smemBuf;                  // [i][o] 64x64
        float* Bs0 = smemBuf + 4096;           // [i][k] 64x64
        float* Bs1 = smemBuf + 8192;

        const float4* a4  = (const float4*)(gA + d * 4096);
        const float4* g40 = (const float4*)(grad + jb0 * 4096);
        const float4* g41 = (const float4*)(grad + jb1 * 4096);
        float4* As4  = (float4*)As;
        float4* Bs04 = (float4*)Bs0;
        float4* Bs14 = (float4*)Bs1;
        #pragma unroll
        for (int idx = tid; idx < 1024; idx += 256) {
            As4[idx] = a4[idx];
            const float4 v0 = g40[idx];
            Bs04[idx] = make_float4(__expf(v0.x), __expf(v0.y), __expf(v0.z), __expf(v0.w));
            const float4 v1 = g41[idx];
            Bs14[idx] = make_float4(__expf(v1.x), __expf(v1.y), __expf(v1.z), __expf(v1.w));
        }
        __syncthreads();

        const int o4 = (tid >> 4) * 4;     // 16 o-groups
        const int k4 = (tid & 15) * 4;     // 16 k-groups
        float acc0[4][4], acc1[4][4];
        #pragma unroll
        for (int oi = 0; oi < 4; oi++)
            #pragma unroll
            for (int kj = 0; kj < 4; kj++) { acc0[oi][kj] = 0.f; acc1[oi][kj] = 0.f; }

        const float* ap  = As  + o4;
        const float* bp0 = Bs0 + k4;
        const float* bp1 = Bs1 + k4;
        #pragma unroll 4
        for (int ii = 0; ii < 64; ii++) {
            const float4 a  = *(const float4*)(ap  + ii * 64);
            const float4 b0 = *(const float4*)(bp0 + ii * 64);
            const float4 b1 = *(const float4*)(bp1 + ii * 64);
            const float av[4] = {a.x,  a.y,  a.z,  a.w};
            const float b0v[4] = {b0.x, b0.y, b0.z, b0.w};
            const float b1v[4] = {b1.x, b1.y, b1.z, b1.w};
            #pragma unroll
            for (int oi = 0; oi < 4; oi++) {
                #pragma unroll
                for (int kj = 0; kj < 4; kj++) {
                    acc0[oi][kj] += av[oi] * b0v[kj];
                    acc1[oi][kj] += av[oi] * b1v[kj];
                }
            }
        }

        float* j0 = outp + 32768 + jb0 * 4096;
        float* j1 = outp + 32768 + jb1 * 4096;
        #pragma unroll
        for (int oi = 0; oi < 4; oi++) {
            float4 v0 = make_float4(__logf(acc0[oi][0]), __logf(acc0[oi][1]),
                                    __logf(acc0[oi][2]), __logf(acc0[oi][3]));
            *(float4*)(j0 + (o4 + oi) * 64 + k4) = v0;
            float4 v1 = make_float4(__logf(acc1[oi][0]), __logf(acc1[oi][1]),
                                    __logf(acc1[oi][2]), __logf(acc1[oi][3]));
            *(float4*)(j1 + (o4 + oi) * 64 + k4) = v1;
        }
    } else {
        // ---------------- out = inputs @ w^T + bias ----------------
        // 32 CTAs: rt = 8 r-tiles x bt = 4 b-tiles (16 batches each)
        const int ob = bid - 256;
        const int rt = ob & 7;
        const int bt = ob >> 3;
        float* sW  = smemBuf;              // [64][68] r-major, float4 k-reads
        float* sIn = smemBuf + 64 * 68;    // [16][64]
        const int b  = tid >> 4;           // 0..15
        const int r4 = (tid & 15) * 4;     // 0..60
        float4 acc[4];
        #pragma unroll
        for (int j = 0; j < 4; j++) acc[j] = make_float4(0.f, 0.f, 0.f, 0.f);

        for (int kc = 0; kc < 8; kc++) {
            #pragma unroll
            for (int idx = tid; idx < 1024; idx += 256) {     // 64x64 tile
                const int row = idx >> 4, c4 = (idx & 15) * 4;
                *(float4*)(sW + row * 68 + c4) =
                    *(const float4*)(gW + (rt * 64 + row) * IN_F + kc * 64 + c4);
            }
            {
                const int idx = tid;                          // 16x64 = 256 f4
                const int row = idx >> 4, c4 = (idx & 15) * 4;
                *(float4*)(sIn + row * 64 + c4) =
                    *(const float4*)(inputs + (bt * 16 + row) * IN_F + kc * 64 + c4);
            }
            __syncthreads();
            #pragma unroll 4
            for (int kk4 = 0; kk4 < 16; kk4++) {
                const float4 iv = *(const float4*)(sIn + b * 64 + kk4 * 4);
                #pragma unroll
                for (int j = 0; j < 4; j++) {
                    const float4 wv = *(const float4*)(sW + (r4 + j) * 68 + kk4 * 4);
                    acc[j].x += iv.x * wv.x;
                    acc[j].y += iv.y * wv.y;
                    acc[j].z += iv.z * wv.z;
                    acc[j].w += iv.w * wv.w;
                }
            }
            __syncthreads();
        }
        const int r = rt * 64 + r4;
        const float4 bv = *(const float4*)(bias + r);
        float4 res;
        res.x = acc[0].x + acc[0].y + acc[0].z + acc[0].w + bv.x;
        res.y = acc[1].x + acc[1].y + acc[1].z + acc[1].w + bv.y;
        res.z = acc[2].x + acc[2].y + acc[2].z + acc[2].w + bv.z;
        res.w = acc[3].x + acc[3].y + acc[3].z + acc[3].w + bv.w;
        *(float4*)(outp + (bt * 16 + b) * OUT_F + r) = res;
    }
}

// ---------------------------------------------------------------------------
// inputs: [0] inputs (64x512 f32), [1] grad (64x8x64x64 f32),
//         [2] W (512x512 f32), [3] diag_w (512 f32), [4] bias (512 f32)
// d_out:  out (64x512) followed by jac (64x8x64x64), f32
// ---------------------------------------------------------------------------
extern "C" void kernel_launch(void* const* d_in, const int* in_sizes, int n_in,
                              void* d_out, int out_size) {
    const float* inputs = (const float*)d_in[0];
    const float* grad   = (const float*)d_in[1];
    const float* W      = (const float*)d_in[2];
    const float* diag_w = (const float*)d_in[3];
    const float* bias   = (const float*)d_in[4];
    float* outp = (float*)d_out;

    k_weights<<<512, 128>>>(W, diag_w);
    k_main<<<256 + 32, 256>>>(grad, inputs, bias, outp);
}

// round 5
// speedup vs baseline: 1.7374x; 1.7374x over previous
#include <cuda_runtime.h>
#include <math.h>

#define BATCH   64
#define IN_F    512
#define OUT_F   512

// Scratch (no allocations allowed -> __device__ globals)
__device__ float gW[OUT_F * IN_F];        // scaled, masked w
__device__ float gA[8 * 64 * 64];         // gA[d][i][o] = exp(g[d,o,i])

// ---------------------------------------------------------------------------
// K1: per-row weight prep. One block (128 thr) per row r of W.
// ---------------------------------------------------------------------------
__global__ void __launch_bounds__(128) k_weights(const float* __restrict__ W,
                                                 const float* __restrict__ diag_w) {
    const int r   = blockIdx.x;
    const int rb  = r >> 6;
    const int lo  = rb << 6;
    const int hi  = lo + 64;
    const int tid = threadIdx.x;

    const float4 wv4 = ((const float4*)(W + r * IN_F))[tid];
    float wv[4] = {wv4.x, wv4.y, wv4.z, wv4.w};
    float wu[4];
    float ss = 0.f;
    #pragma unroll
    for (int j = 0; j < 4; j++) {
        const int c = tid * 4 + j;
        float u;
        if (c >= hi)      u = 0.f;
        else if (c >= lo) u = __expf(wv[j]);
        else              u = wv[j];
        wu[j] = u;
        ss += u * u;
    }
    #pragma unroll
    for (int off = 16; off > 0; off >>= 1)
        ss += __shfl_down_sync(0xffffffffu, ss, off);
    __shared__ float sred[4];
    __shared__ float sbc[2];
    if ((tid & 31) == 0) sred[tid >> 5] = ss;
    __syncthreads();
    if (tid == 0) {
        const float wsn = sred[0] + sred[1] + sred[2] + sred[3];
        const float dv  = diag_w[r];
        sbc[0] = __expf(dv) * rsqrtf(wsn);       // row scale for w
        sbc[1] = dv - 0.5f * __logf(wsn);        // c1 for g
    }
    __syncthreads();
    const float scale = sbc[0];
    const float c1    = sbc[1];
    float4 o4 = make_float4(scale * wu[0], scale * wu[1], scale * wu[2], scale * wu[3]);
    ((float4*)(gW + r * IN_F))[tid] = o4;
    #pragma unroll
    for (int j = 0; j < 4; j++) {
        const int c = tid * 4 + j;
        if (c >= lo && c < hi) {
            const int i = c - lo;
            gA[(rb * 64 + i) * 64 + (r - lo)] = __expf(c1 + wv[j]);   // [d][i][o]
        }
    }
}

// ---------------------------------------------------------------------------
// K2 fused, 256 threads:
//   bid <  64 : out tile (8b x 64r, full K=512, bias inline)
//   bid >= 64 : jac for (b,d) pair jbid = bid-64  (EXACT R1 inner loop)
// ---------------------------------------------------------------------------
__global__ void __launch_bounds__(256) k_main(
        const float* __restrict__ grad,
        const float* __restrict__ inputs,
        const float* __restrict__ bias,
        float* __restrict__ outp) {
    __shared__ float smemBuf[8192];      // 32 KB
    const int bid = blockIdx.x;
    const int tid = threadIdx.x;

    if (bid >= 64) {
        // ---------------- jac: C = gA[d]^T @ exp(grad_b);  log ----------------
        const int jbid = bid - 64;       // = b*8 + d
        const int d    = jbid & 7;
        float* As = smemBuf;             // [i][o]  64x64
        float* Bs = smemBuf + 4096;      // [i][k]  64x64

        const float4* a4 = (const float4*)(gA + d * 4096);
        const float4* g4 = (const float4*)(grad + jbid * 4096);
        float4* As4 = (float4*)As;
        float4* Bs4 = (float4*)Bs;
        #pragma unroll
        for (int idx = tid; idx < 1024; idx += 256) {
            As4[idx] = a4[idx];
            const float4 v = g4[idx];
            Bs4[idx] = make_float4(__expf(v.x), __expf(v.y), __expf(v.z), __expf(v.w));
        }
        __syncthreads();

        const int k_t = tid & 15;        // 16 x4 -> 64 k
        const int o_t = tid >> 4;        // 16 x4 -> 64 o
        float acc[4][4] = {};
        const float* ap = As + o_t * 4;
        const float* bp = Bs + k_t * 4;
        #pragma unroll 8
        for (int ii = 0; ii < 64; ii++) {
            const float4 a  = *(const float4*)(ap + ii * 64);
            const float4 bv = *(const float4*)(bp + ii * 64);
            acc[0][0] += a.x * bv.x; acc[0][1] += a.x * bv.y; acc[0][2] += a.x * bv.z; acc[0][3] += a.x * bv.w;
            acc[1][0] += a.y * bv.x; acc[1][1] += a.y * bv.y; acc[1][2] += a.y * bv.z; acc[1][3] += a.y * bv.w;
            acc[2][0] += a.z * bv.x; acc[2][1] += a.z * bv.y; acc[2][2] += a.z * bv.z; acc[2][3] += a.z * bv.w;
            acc[3][0] += a.w * bv.x; acc[3][1] += a.w * bv.y; acc[3][2] += a.w * bv.z; acc[3][3] += a.w * bv.w;
        }

        float* jb = outp + 32768 + jbid * 4096;   // jac block [o][k]
        #pragma unroll
        for (int jo = 0; jo < 4; jo++) {
            const int o = o_t * 4 + jo;
            float4 v = make_float4(__logf(acc[jo][0]), __logf(acc[jo][1]),
                                   __logf(acc[jo][2]), __logf(acc[jo][3]));
            *(float4*)(jb + o * 64 + k_t * 4) = v;
        }
    } else {
        // ---------------- out = inputs @ w^T + bias ----------------
        float* sW  = smemBuf;            // [64][65] padded
        float* sIn = smemBuf + 64 * 65;  // [8][64]
        const int rt = bid >> 3;         // 0..7 : r-tile
        const int bt = bid & 7;          // 0..7 : batch tile (8 rows)
        const int b  = tid >> 5;         // 0..7
        const int r2 = (tid & 31) * 2;   // 0,2,..,62
        float acc0 = 0.f, acc1 = 0.f;

        for (int kc = 0; kc < 8; kc++) {
            #pragma unroll
            for (int idx = tid; idx < 1024; idx += 256) {   // 64x64 gW tile (f4)
                const int row = idx >> 4, c4 = (idx & 15) * 4;
                const float4 v = *(const float4*)(gW + (rt * 64 + row) * IN_F + kc * 64 + c4);
                float* dst = sW + row * 65 + c4;
                dst[0] = v.x; dst[1] = v.y; dst[2] = v.z; dst[3] = v.w;
            }
            if (tid < 128) {                                // 8x64 inputs tile (f4)
                const int row = tid >> 4, c4 = (tid & 15) * 4;
                *(float4*)(sIn + row * 64 + c4) =
                    *(const float4*)(inputs + (bt * 8 + row) * IN_F + kc * 64 + c4);
            }
            __syncthreads();
            #pragma unroll 8
            for (int kk = 0; kk < 64; kk++) {
                const float iv = sIn[b * 64 + kk];
                acc0 += iv * sW[r2 * 65 + kk];
                acc1 += iv * sW[(r2 + 1) * 65 + kk];
            }
            __syncthreads();
        }
        const int r = rt * 64 + r2;
        float* orow = outp + (bt * 8 + b) * OUT_F + r;
        orow[0] = acc0 + bias[r];
        orow[1] = acc1 + bias[r + 1];
    }
}

// ---------------------------------------------------------------------------
// inputs: [0] inputs (64x512 f32), [1] grad (64x8x64x64 f32),
//         [2] W (512x512 f32), [3] diag_w (512 f32), [4] bias (512 f32)
// d_out:  out (64x512) followed by jac (64x8x64x64), f32
// ---------------------------------------------------------------------------
extern "C" void kernel_launch(void* const* d_in, const int* in_sizes, int n_in,
                              void* d_out, int out_size) {
    const float* inputs = (const float*)d_in[0];
    const float* grad   = (const float*)d_in[1];
    const float* W      = (const float*)d_in[2];
    const float* diag_w = (const float*)d_in[3];
    const float* bias   = (const float*)d_in[4];
    float* outp = (float*)d_out;

    k_weights<<<512, 128>>>(W, diag_w);
    k_main<<<512 + 64, 256>>>(grad, inputs, bias, outp);
}

// round 6
// speedup vs baseline: 2.3960x; 1.3790x over previous
#include <cuda_runtime.h>
#include <math.h>

#define BATCH   64
#define IN_F    512
#define OUT_F   512

// Scratch (no allocations allowed -> __device__ globals)
__device__ float gWT[IN_F * OUT_F];       // gWT[k][r] = w[r][k]   (transposed)
__device__ float gInT[IN_F * BATCH];      // gInT[k][b] = inputs[b][k]
__device__ float gA[8 * 64 * 64];         // gA[d][i][o] = exp(g[d,o,i])
__device__ float gPart[8 * BATCH * OUT_F];// out partials [kc][b][r]

// ---------------------------------------------------------------------------
// K1: bid < 512 : per-row weight prep (row r), writes gWT transposed + gA.
//     bid >= 512: transpose inputs -> gInT (64 CTAs, one batch each).
// ---------------------------------------------------------------------------
__global__ void __launch_bounds__(128) k_weights(const float* __restrict__ W,
                                                 const float* __restrict__ diag_w,
                                                 const float* __restrict__ inputs) {
    const int tid = threadIdx.x;
    if (blockIdx.x >= 512) {
        const int b = blockIdx.x - 512;
        const float4 v = ((const float4*)(inputs + b * IN_F))[tid];
        const int k0 = tid * 4;
        gInT[(k0 + 0) * BATCH + b] = v.x;
        gInT[(k0 + 1) * BATCH + b] = v.y;
        gInT[(k0 + 2) * BATCH + b] = v.z;
        gInT[(k0 + 3) * BATCH + b] = v.w;
        return;
    }
    const int r   = blockIdx.x;
    const int rb  = r >> 6;
    const int lo  = rb << 6;
    const int hi  = lo + 64;

    const float4 wv4 = ((const float4*)(W + r * IN_F))[tid];
    float wv[4] = {wv4.x, wv4.y, wv4.z, wv4.w};
    float wu[4];
    float ss = 0.f;
    #pragma unroll
    for (int j = 0; j < 4; j++) {
        const int c = tid * 4 + j;
        float u;
        if (c >= hi)      u = 0.f;
        else if (c >= lo) u = __expf(wv[j]);
        else              u = wv[j];
        wu[j] = u;
        ss += u * u;
    }
    #pragma unroll
    for (int off = 16; off > 0; off >>= 1)
        ss += __shfl_down_sync(0xffffffffu, ss, off);
    __shared__ float sred[4];
    __shared__ float sbc[2];
    if ((tid & 31) == 0) sred[tid >> 5] = ss;
    __syncthreads();
    if (tid == 0) {
        const float wsn = sred[0] + sred[1] + sred[2] + sred[3];
        const float dv  = diag_w[r];
        sbc[0] = __expf(dv) * rsqrtf(wsn);       // row scale for w
        sbc[1] = dv - 0.5f * __logf(wsn);        // c1 for g
    }
    __syncthreads();
    const float scale = sbc[0];
    const float c1    = sbc[1];
    #pragma unroll
    for (int j = 0; j < 4; j++) {
        const int c = tid * 4 + j;
        gWT[c * OUT_F + r] = scale * wu[j];                    // transposed store
        if (c >= lo && c < hi) {
            const int i = c - lo;
            gA[(rb * 64 + i) * 64 + (r - lo)] = __expf(c1 + wv[j]);   // [d][i][o]
        }
    }
}

// ---------------------------------------------------------------------------
// K2 fused, 256 threads:
//   bid <  64 : out partial, CTA = (rt, kc): 64r x 64b x 64k, FMA-dense
//   bid >= 64 : jac for (b,d) pair jbid = bid-64  (proven R1 loop)
// ---------------------------------------------------------------------------
__global__ void __launch_bounds__(256) k_main(
        const float* __restrict__ grad,
        float* __restrict__ outp) {
    __shared__ float smemBuf[8704];      // out: 2x 64*68; jac: 2x 4096
    const int bid = blockIdx.x;
    const int tid = threadIdx.x;

    if (bid >= 64) {
        // ---------------- jac: C = gA[d]^T @ exp(grad_b);  log ----------------
        const int jbid = bid - 64;       // = b*8 + d
        const int d    = jbid & 7;
        float* As = smemBuf;             // [i][o]  64x64
        float* Bs = smemBuf + 4096;      // [i][k]  64x64

        const float4* a4 = (const float4*)(gA + d * 4096);
        const float4* g4 = (const float4*)(grad + jbid * 4096);
        float4* As4 = (float4*)As;
        float4* Bs4 = (float4*)Bs;
        #pragma unroll
        for (int idx = tid; idx < 1024; idx += 256) {
            As4[idx] = a4[idx];
            const float4 v = g4[idx];
            Bs4[idx] = make_float4(__expf(v.x), __expf(v.y), __expf(v.z), __expf(v.w));
        }
        __syncthreads();

        const int k_t = tid & 15;        // 16 x4 -> 64 k
        const int o_t = tid >> 4;        // 16 x4 -> 64 o
        float acc[4][4] = {};
        const float* ap = As + o_t * 4;
        const float* bp = Bs + k_t * 4;
        #pragma unroll 8
        for (int ii = 0; ii < 64; ii++) {
            const float4 a  = *(const float4*)(ap + ii * 64);
            const float4 bv = *(const float4*)(bp + ii * 64);
            acc[0][0] += a.x * bv.x; acc[0][1] += a.x * bv.y; acc[0][2] += a.x * bv.z; acc[0][3] += a.x * bv.w;
            acc[1][0] += a.y * bv.x; acc[1][1] += a.y * bv.y; acc[1][2] += a.y * bv.z; acc[1][3] += a.y * bv.w;
            acc[2][0] += a.z * bv.x; acc[2][1] += a.z * bv.y; acc[2][2] += a.z * bv.z; acc[2][3] += a.z * bv.w;
            acc[3][0] += a.w * bv.x; acc[3][1] += a.w * bv.y; acc[3][2] += a.w * bv.z; acc[3][3] += a.w * bv.w;
        }

        float* jb = outp + 32768 + jbid * 4096;   // jac block [o][k]
        #pragma unroll
        for (int jo = 0; jo < 4; jo++) {
            const int o = o_t * 4 + jo;
            float4 v = make_float4(__logf(acc[jo][0]), __logf(acc[jo][1]),
                                   __logf(acc[jo][2]), __logf(acc[jo][3]));
            *(float4*)(jb + o * 64 + k_t * 4) = v;
        }
    } else {
        // ---------------- out partial: 64r x 64b over one 64-k chunk ----------
        const int rt = bid & 7;
        const int kc = bid >> 3;
        float* sWT  = smemBuf;              // [kk][r] 64x68
        float* sInT = smemBuf + 64 * 68;    // [kk][b] 64x68  (4352 offset)

        // fills: coalesced LDG.128, conflict-free STS.128 (no transpose needed)
        #pragma unroll
        for (int idx = tid; idx < 1024; idx += 256) {
            const int kk = idx >> 4, c4 = (idx & 15) * 4;
            *(float4*)(sWT + kk * 68 + c4) =
                *(const float4*)(gWT + (kc * 64 + kk) * OUT_F + rt * 64 + c4);
        }
        #pragma unroll
        for (int idx = tid; idx < 1024; idx += 256) {
            const int kk = idx >> 4, c4 = (idx & 15) * 4;
            *(float4*)(sInT + kk * 68 + c4) =
                *(const float4*)(gInT + (kc * 64 + kk) * BATCH + c4);
        }
        __syncthreads();

        const int b4 = (tid & 15) * 4;   // 16 -> 64 b
        const int r4 = (tid >> 4) * 4;   // 16 -> 64 r
        float acc[4][4] = {};            // [bi][ri]
        const float* ip = sInT + b4;
        const float* wp = sWT + r4;
        #pragma unroll 8
        for (int kk = 0; kk < 64; kk++) {
            const float4 iv = *(const float4*)(ip + kk * 68);
            const float4 wv = *(const float4*)(wp + kk * 68);
            acc[0][0] += iv.x * wv.x; acc[0][1] += iv.x * wv.y; acc[0][2] += iv.x * wv.z; acc[0][3] += iv.x * wv.w;
            acc[1][0] += iv.y * wv.x; acc[1][1] += iv.y * wv.y; acc[1][2] += iv.y * wv.z; acc[1][3] += iv.y * wv.w;
            acc[2][0] += iv.z * wv.x; acc[2][1] += iv.z * wv.y; acc[2][2] += iv.z * wv.z; acc[2][3] += iv.z * wv.w;
            acc[3][0] += iv.w * wv.x; acc[3][1] += iv.w * wv.y; acc[3][2] += iv.w * wv.z; acc[3][3] += iv.w * wv.w;
        }

        float* part = gPart + kc * (BATCH * OUT_F) + rt * 64;
        #pragma unroll
        for (int bi = 0; bi < 4; bi++) {
            float4 v = make_float4(acc[bi][0], acc[bi][1], acc[bi][2], acc[bi][3]);
            *(float4*)(part + (b4 + bi) * OUT_F + r4) = v;
        }
    }
}

// ---------------------------------------------------------------------------
// K3: reduce 8 k-chunk partials + bias -> out (first 32768 floats), float4
// ---------------------------------------------------------------------------
__global__ void __launch_bounds__(256) k_reduce(const float* __restrict__ bias,
                                                float* __restrict__ outp) {
    const int t    = blockIdx.x * 256 + threadIdx.x;   // < 8192
    const int idx4 = t * 4;
    float4 s = *(const float4*)(bias + (idx4 & 511));
    #pragma unroll
    for (int kc = 0; kc < 8; kc++) {
        const float4 p = *(const float4*)(gPart + kc * (BATCH * OUT_F) + idx4);
        s.x += p.x; s.y += p.y; s.z += p.z; s.w += p.w;
    }
    *(float4*)(outp + idx4) = s;
}

// ---------------------------------------------------------------------------
// inputs: [0] inputs (64x512 f32), [1] grad (64x8x64x64 f32),
//         [2] W (512x512 f32), [3] diag_w (512 f32), [4] bias (512 f32)
// d_out:  out (64x512) followed by jac (64x8x64x64), f32
// ---------------------------------------------------------------------------
extern "C" void kernel_launch(void* const* d_in, const int* in_sizes, int n_in,
                              void* d_out, int out_size) {
    const float* inputs = (const float*)d_in[0];
    const float* grad   = (const float*)d_in[1];
    const float* W      = (const float*)d_in[2];
    const float* diag_w = (const float*)d_in[3];
    const float* bias   = (const float*)d_in[4];
    float* outp = (float*)d_out;

    k_weights<<<512 + 64, 128>>>(W, diag_w, inputs);
    k_main<<<512 + 64, 256>>>(grad, outp);
    k_reduce<<<32, 256>>>(bias, outp);
}

// round 7
// speedup vs baseline: 2.4109x; 1.0062x over previous
#include <cuda_runtime.h>
#include <math.h>

#define BATCH   64
#define IN_F    512
#define OUT_F   512

// Scratch (no allocations allowed -> __device__ globals)
__device__ float gWT[IN_F * OUT_F];       // gWT[k][r] = w[r][k]   (transposed)
__device__ float gInT[IN_F * BATCH];      // gInT[k][b] = inputs[b][k]
__device__ float gA[8 * 64 * 64];         // gA[d][i][o] = exp(g[d,o,i]) = scaled diag block
__device__ float gPart[8 * BATCH * OUT_F];// out partials [kc][b][r]

// ---------------------------------------------------------------------------
// K1: bid < 64 : 8 weight rows per CTA (warp-per-row).
//       u = exp(W) on diag / W below / 0 above;  wsn = sum u^2 (warp butterfly)
//       scale = exp(diag_w)*rsqrt(wsn).  Staged unscaled in sT, then one
//       coalesced transposed writeback of scale*u to gWT (and gA on diag:
//       exp(wpl) == scaled diag block -- algebraic identity, no extra exp).
//     bid >= 64 (8 CTAs): warp-per-batch input transpose -> gInT.
// ---------------------------------------------------------------------------
__global__ void __launch_bounds__(256) k_weights(const float* __restrict__ W,
                                                 const float* __restrict__ diag_w,
                                                 const float* __restrict__ inputs) {
    const int tid  = threadIdx.x;
    const int w    = tid >> 5;
    const int lane = tid & 31;

    if (blockIdx.x >= 64) {
        // -------- input transpose: 8 warps, warp = one batch row --------
        const int b = (blockIdx.x - 64) * 8 + w;
        #pragma unroll
        for (int m = 0; m < 4; m++) {
            const int c0 = lane * 4 + m * 128;
            const float4 v = *(const float4*)(inputs + b * IN_F + c0);
            gInT[(c0 + 0) * BATCH + b] = v.x;
            gInT[(c0 + 1) * BATCH + b] = v.y;
            gInT[(c0 + 2) * BATCH + b] = v.z;
            gInT[(c0 + 3) * BATCH + b] = v.w;
        }
        return;
    }

    __shared__ float sT[512 * 9];        // [c][w] unscaled u, pad 9
    __shared__ float sScale[8];

    const int r  = blockIdx.x * 8 + w;
    const int rb = r >> 6;
    const int lo = rb << 6;
    const int hi = lo + 64;

    float ss = 0.f;
    #pragma unroll
    for (int m = 0; m < 4; m++) {
        const int c0 = lane * 4 + m * 128;
        const float4 v = *(const float4*)(W + r * IN_F + c0);
        const float vv[4] = {v.x, v.y, v.z, v.w};
        #pragma unroll
        for (int j = 0; j < 4; j++) {
            const int c = c0 + j;
            float u;
            if (c >= hi)      u = 0.f;
            else if (c >= lo) u = __expf(vv[j]);
            else              u = vv[j];
            ss += u * u;
            sT[c * 9 + w] = u;
        }
    }
    #pragma unroll
    for (int off = 16; off > 0; off >>= 1)
        ss += __shfl_xor_sync(0xffffffffu, ss, off);
    if (lane == 0)
        sScale[w] = __expf(diag_w[r]) * rsqrtf(ss);
    __syncthreads();

    // -------- transposed, coalesced writeback: 2 c-values per thread --------
    float sc[8];
    #pragma unroll
    for (int j = 0; j < 8; j++) sc[j] = sScale[j];
    const int rbase = blockIdx.x * 8;            // global row start (8 rows)
    const int obase = (blockIdx.x & 7) * 8;      // o start within dim block
    #pragma unroll
    for (int cc = tid * 2; cc < tid * 2 + 2; cc++) {
        float v[8];
        #pragma unroll
        for (int j = 0; j < 8; j++) v[j] = sT[cc * 9 + j] * sc[j];
        float4 v0 = make_float4(v[0], v[1], v[2], v[3]);
        float4 v1 = make_float4(v[4], v[5], v[6], v[7]);
        *(float4*)(gWT + cc * OUT_F + rbase)     = v0;
        *(float4*)(gWT + cc * OUT_F + rbase + 4) = v1;
        if (cc >= lo && cc < hi) {               // gA[d][i][o] = scaled diag
            float* gp = gA + (rb * 64 + (cc - lo)) * 64 + obase;
            *(float4*)gp       = v0;
            *(float4*)(gp + 4) = v1;
        }
    }
}

// ---------------------------------------------------------------------------
// K2 fused, 256 threads:
//   bid <  64 : out partial, CTA = (rt, kc): 64r x 64b x 64k, FMA-dense
//   bid >= 64 : jac for (b,d) pair jbid = bid-64  (proven loop)
// ---------------------------------------------------------------------------
__global__ void __launch_bounds__(256) k_main(
        const float* __restrict__ grad,
        float* __restrict__ outp) {
    __shared__ float smemBuf[8704];
    const int bid = blockIdx.x;
    const int tid = threadIdx.x;

    if (bid >= 64) {
        // ---------------- jac: C = gA[d]^T @ exp(grad_b);  log ----------------
        const int jbid = bid - 64;       // = b*8 + d
        const int d    = jbid & 7;
        float* As = smemBuf;             // [i][o]  64x64
        float* Bs = smemBuf + 4096;      // [i][k]  64x64

        const float4* a4 = (const float4*)(gA + d * 4096);
        const float4* g4 = (const float4*)(grad + jbid * 4096);
        float4* As4 = (float4*)As;
        float4* Bs4 = (float4*)Bs;
        #pragma unroll
        for (int idx = tid; idx < 1024; idx += 256) {
            As4[idx] = a4[idx];
            const float4 v = g4[idx];
            Bs4[idx] = make_float4(__expf(v.x), __expf(v.y), __expf(v.z), __expf(v.w));
        }
        __syncthreads();

        const int k_t = tid & 15;        // 16 x4 -> 64 k
        const int o_t = tid >> 4;        // 16 x4 -> 64 o
        float acc[4][4] = {};
        const float* ap = As + o_t * 4;
        const float* bp = Bs + k_t * 4;
        #pragma unroll 8
        for (int ii = 0; ii < 64; ii++) {
            const float4 a  = *(const float4*)(ap + ii * 64);
            const float4 bv = *(const float4*)(bp + ii * 64);
            acc[0][0] += a.x * bv.x; acc[0][1] += a.x * bv.y; acc[0][2] += a.x * bv.z; acc[0][3] += a.x * bv.w;
            acc[1][0] += a.y * bv.x; acc[1][1] += a.y * bv.y; acc[1][2] += a.y * bv.z; acc[1][3] += a.y * bv.w;
            acc[2][0] += a.z * bv.x; acc[2][1] += a.z * bv.y; acc[2][2] += a.z * bv.z; acc[2][3] += a.z * bv.w;
            acc[3][0] += a.w * bv.x; acc[3][1] += a.w * bv.y; acc[3][2] += a.w * bv.z; acc[3][3] += a.w * bv.w;
        }

        float* jb = outp + 32768 + jbid * 4096;   // jac block [o][k]
        #pragma unroll
        for (int jo = 0; jo < 4; jo++) {
            const int o = o_t * 4 + jo;
            float4 v = make_float4(__logf(acc[jo][0]), __logf(acc[jo][1]),
                                   __logf(acc[jo][2]), __logf(acc[jo][3]));
            *(float4*)(jb + o * 64 + k_t * 4) = v;
        }
    } else {
        // ---------------- out partial: 64r x 64b over one 64-k chunk ----------
        const int rt = bid & 7;
        const int kc = bid >> 3;
        float* sWT  = smemBuf;              // [kk][r] 64x68
        float* sInT = smemBuf + 64 * 68;    // [kk][b] 64x68

        #pragma unroll
        for (int idx = tid; idx < 1024; idx += 256) {
            const int kk = idx >> 4, c4 = (idx & 15) * 4;
            *(float4*)(sWT + kk * 68 + c4) =
                *(const float4*)(gWT + (kc * 64 + kk) * OUT_F + rt * 64 + c4);
        }
        #pragma unroll
        for (int idx = tid; idx < 1024; idx += 256) {
            const int kk = idx >> 4, c4 = (idx & 15) * 4;
            *(float4*)(sInT + kk * 68 + c4) =
                *(const float4*)(gInT + (kc * 64 + kk) * BATCH + c4);
        }
        __syncthreads();

        const int b4 = (tid & 15) * 4;   // 16 -> 64 b
        const int r4 = (tid >> 4) * 4;   // 16 -> 64 r
        float acc[4][4] = {};            // [bi][ri]
        const float* ip = sInT + b4;
        const float* wp = sWT + r4;
        #pragma unroll 8
        for (int kk = 0; kk < 64; kk++) {
            const float4 iv = *(const float4*)(ip + kk * 68);
            const float4 wv = *(const float4*)(wp + kk * 68);
            acc[0][0] += iv.x * wv.x; acc[0][1] += iv.x * wv.y; acc[0][2] += iv.x * wv.z; acc[0][3] += iv.x * wv.w;
            acc[1][0] += iv.y * wv.x; acc[1][1] += iv.y * wv.y; acc[1][2] += iv.y * wv.z; acc[1][3] += iv.y * wv.w;
            acc[2][0] += iv.z * wv.x; acc[2][1] += iv.z * wv.y; acc[2][2] += iv.z * wv.z; acc[2][3] += iv.z * wv.w;
            acc[3][0] += iv.w * wv.x; acc[3][1] += iv.w * wv.y; acc[3][2] += iv.w * wv.z; acc[3][3] += iv.w * wv.w;
        }

        float* part = gPart + kc * (BATCH * OUT_F) + rt * 64;
        #pragma unroll
        for (int bi = 0; bi < 4; bi++) {
            float4 v = make_float4(acc[bi][0], acc[bi][1], acc[bi][2], acc[bi][3]);
            *(float4*)(part + (b4 + bi) * OUT_F + r4) = v;
        }
    }
}

// ---------------------------------------------------------------------------
// K3: reduce 8 k-chunk partials + bias -> out (first 32768 floats), float4
// ---------------------------------------------------------------------------
__global__ void __launch_bounds__(256) k_reduce(const float* __restrict__ bias,
                                                float* __restrict__ outp) {
    const int t    = blockIdx.x * 256 + threadIdx.x;   // < 8192
    const int idx4 = t * 4;
    float4 s = *(const float4*)(bias + (idx4 & 511));
    #pragma unroll
    for (int kc = 0; kc < 8; kc++) {
        const float4 p = *(const float4*)(gPart + kc * (BATCH * OUT_F) + idx4);
        s.x += p.x; s.y += p.y; s.z += p.z; s.w += p.w;
    }
    *(float4*)(outp + idx4) = s;
}

// ---------------------------------------------------------------------------
// inputs: [0] inputs (64x512 f32), [1] grad (64x8x64x64 f32),
//         [2] W (512x512 f32), [3] diag_w (512 f32), [4] bias (512 f32)
// d_out:  out (64x512) followed by jac (64x8x64x64), f32
// ---------------------------------------------------------------------------
extern "C" void kernel_launch(void* const* d_in, const int* in_sizes, int n_in,
                              void* d_out, int out_size) {
    const float* inputs = (const float*)d_in[0];
    const float* grad   = (const float*)d_in[1];
    const float* W      = (const float*)d_in[2];
    const float* diag_w = (const float*)d_in[3];
    const float* bias   = (const float*)d_in[4];
    float* outp = (float*)d_out;

    k_weights<<<64 + 8, 256>>>(W, diag_w, inputs);
    k_main<<<512 + 64, 256>>>(grad, outp);
    k_reduce<<<32, 256>>>(bias, outp);
}

// round 8
// speedup vs baseline: 2.4259x; 1.0062x over previous
#include <cuda_runtime.h>
#include <math.h>

#define BATCH   64
#define IN_F    512
#define OUT_F   512

// Scratch (no allocations allowed -> __device__ globals)
__device__ float gW[OUT_F * IN_F];        // scaled masked w, row-major
__device__ float gInT[IN_F * BATCH];      // gInT[k][b] = inputs[b][k]
__device__ float gA[8 * 64 * 64];         // gA[d][i][o] = exp(g[d,o,i]) = scaled diag block
__device__ float gPart[8 * BATCH * OUT_F];// out partials [kc][b][r]

// ---------------------------------------------------------------------------
// K1: bid < 64 : warp-per-row weight prep, REGISTER-ONLY (no smem/syncs).
//       u = exp(W) on diag / W below / 0 above; wsn = warp butterfly;
//       scale = exp(diag_w)*rsqrt(wsn); coalesced float4 STG to gW row-major.
//       gA (= scaled diag block, algebraic identity) small scattered stores.
//     bid >= 64 (8 CTAs): warp-per-batch input transpose -> gInT.
// ---------------------------------------------------------------------------
__global__ void __launch_bounds__(256) k_weights(const float* __restrict__ W,
                                                 const float* __restrict__ diag_w,
                                                 const float* __restrict__ inputs) {
    const int tid  = threadIdx.x;
    const int w    = tid >> 5;
    const int lane = tid & 31;

    if (blockIdx.x >= 64) {
        // -------- input transpose: 8 warps, warp = one batch row --------
        const int b = (blockIdx.x - 64) * 8 + w;
        #pragma unroll
        for (int m = 0; m < 4; m++) {
            const int c0 = lane * 4 + m * 128;
            const float4 v = *(const float4*)(inputs + b * IN_F + c0);
            gInT[(c0 + 0) * BATCH + b] = v.x;
            gInT[(c0 + 1) * BATCH + b] = v.y;
            gInT[(c0 + 2) * BATCH + b] = v.z;
            gInT[(c0 + 3) * BATCH + b] = v.w;
        }
        return;
    }

    const int r  = blockIdx.x * 8 + w;
    const int rb = r >> 6;
    const int lo = rb << 6;
    const int hi = lo + 64;

    float uu[4][4];
    float ss = 0.f;
    #pragma unroll
    for (int m = 0; m < 4; m++) {
        const int c0 = lane * 4 + m * 128;
        const float4 v = *(const float4*)(W + r * IN_F + c0);
        const float vv[4] = {v.x, v.y, v.z, v.w};
        #pragma unroll
        for (int j = 0; j < 4; j++) {
            const int c = c0 + j;
            float u;
            if (c >= hi)      u = 0.f;
            else if (c >= lo) u = __expf(vv[j]);
            else              u = vv[j];
            uu[m][j] = u;
            ss += u * u;
        }
    }
    #pragma unroll
    for (int off = 16; off > 0; off >>= 1)
        ss += __shfl_xor_sync(0xffffffffu, ss, off);
    const float scale = __expf(diag_w[r]) * rsqrtf(ss);

    const int o = r - lo;
    #pragma unroll
    for (int m = 0; m < 4; m++) {
        const int c0 = lane * 4 + m * 128;
        float4 o4 = make_float4(scale * uu[m][0], scale * uu[m][1],
                                scale * uu[m][2], scale * uu[m][3]);
        *(float4*)(gW + r * IN_F + c0) = o4;
        const float ov[4] = {o4.x, o4.y, o4.z, o4.w};
        #pragma unroll
        for (int j = 0; j < 4; j++) {
            const int c = c0 + j;
            if (c >= lo && c < hi)
                gA[(rb * 64 + (c - lo)) * 64 + o] = ov[j];   // [d][i][o]
        }
    }
}

// ---------------------------------------------------------------------------
// K2 fused, 256 threads:
//   bid <  64 : out partial, CTA = (rt, kc); smem-transposed fills from gW
//   bid >= 64 : jac for (b,d) pair jbid = bid-64  (proven loop, untouched)
// ---------------------------------------------------------------------------
__global__ void __launch_bounds__(256) k_main(
        const float* __restrict__ grad,
        float* __restrict__ outp) {
    __shared__ float smemBuf[8704];
    const int bid = blockIdx.x;
    const int tid = threadIdx.x;

    if (bid >= 64) {
        // ---------------- jac: C = gA[d]^T @ exp(grad_b);  log ----------------
        const int jbid = bid - 64;       // = b*8 + d
        const int d    = jbid & 7;
        float* As = smemBuf;             // [i][o]  64x64
        float* Bs = smemBuf + 4096;      // [i][k]  64x64

        const float4* a4 = (const float4*)(gA + d * 4096);
        const float4* g4 = (const float4*)(grad + jbid * 4096);
        float4* As4 = (float4*)As;
        float4* Bs4 = (float4*)Bs;
        #pragma unroll
        for (int idx = tid; idx < 1024; idx += 256) {
            As4[idx] = a4[idx];
            const float4 v = g4[idx];
            Bs4[idx] = make_float4(__expf(v.x), __expf(v.y), __expf(v.z), __expf(v.w));
        }
        __syncthreads();

        const int k_t = tid & 15;        // 16 x4 -> 64 k
        const int o_t = tid >> 4;        // 16 x4 -> 64 o
        float acc[4][4] = {};
        const float* ap = As + o_t * 4;
        const float* bp = Bs + k_t * 4;
        #pragma unroll 8
        for (int ii = 0; ii < 64; ii++) {
            const float4 a  = *(const float4*)(ap + ii * 64);
            const float4 bv = *(const float4*)(bp + ii * 64);
            acc[0][0] += a.x * bv.x; acc[0][1] += a.x * bv.y; acc[0][2] += a.x * bv.z; acc[0][3] += a.x * bv.w;
            acc[1][0] += a.y * bv.x; acc[1][1] += a.y * bv.y; acc[1][2] += a.y * bv.z; acc[1][3] += a.y * bv.w;
            acc[2][0] += a.z * bv.x; acc[2][1] += a.z * bv.y; acc[2][2] += a.z * bv.z; acc[2][3] += a.z * bv.w;
            acc[3][0] += a.w * bv.x; acc[3][1] += a.w * bv.y; acc[3][2] += a.w * bv.z; acc[3][3] += a.w * bv.w;
        }

        float* jb = outp + 32768 + jbid * 4096;   // jac block [o][k]
        #pragma unroll
        for (int jo = 0; jo < 4; jo++) {
            const int o = o_t * 4 + jo;
            float4 v = make_float4(__logf(acc[jo][0]), __logf(acc[jo][1]),
                                   __logf(acc[jo][2]), __logf(acc[jo][3]));
            *(float4*)(jb + o * 64 + k_t * 4) = v;
        }
    } else {
        // ---------------- out partial: 64r x 64b over one 64-k chunk ----------
        const int rt = bid & 7;
        const int kc = bid >> 3;
        float* sWT  = smemBuf;              // [kk][r] 64x68
        float* sInT = smemBuf + 64 * 68;    // [kk][b] 64x68

        // W fill: coalesced LDG from row-major gW, transposed STS
        #pragma unroll
        for (int m = 0; m < 4; m++) {
            const int idx = tid + 256 * m;            // 1024 float4
            const int rr = idx >> 4, kq = (idx & 15) * 4;
            const float4 v = *(const float4*)(gW + (rt * 64 + rr) * IN_F + kc * 64 + kq);
            sWT[(kq + 0) * 68 + rr] = v.x;
            sWT[(kq + 1) * 68 + rr] = v.y;
            sWT[(kq + 2) * 68 + rr] = v.z;
            sWT[(kq + 3) * 68 + rr] = v.w;
        }
        // inputs fill: already transposed in gInT, straight copy
        #pragma unroll
        for (int m = 0; m < 4; m++) {
            const int idx = tid + 256 * m;
            const int kk = idx >> 4, c4 = (idx & 15) * 4;
            *(float4*)(sInT + kk * 68 + c4) =
                *(const float4*)(gInT + (kc * 64 + kk) * BATCH + c4);
        }
        __syncthreads();

        const int b4 = (tid & 15) * 4;   // 16 -> 64 b
        const int r4 = (tid >> 4) * 4;   // 16 -> 64 r
        float acc[4][4] = {};            // [bi][ri]
        const float* ip = sInT + b4;
        const float* wp = sWT + r4;
        #pragma unroll 8
        for (int kk = 0; kk < 64; kk++) {
            const float4 iv = *(const float4*)(ip + kk * 68);
            const float4 wv = *(const float4*)(wp + kk * 68);
            acc[0][0] += iv.x * wv.x; acc[0][1] += iv.x * wv.y; acc[0][2] += iv.x * wv.z; acc[0][3] += iv.x * wv.w;
            acc[1][0] += iv.y * wv.x; acc[1][1] += iv.y * wv.y; acc[1][2] += iv.y * wv.z; acc[1][3] += iv.y * wv.w;
            acc[2][0] += iv.z * wv.x; acc[2][1] += iv.z * wv.y; acc[2][2] += iv.z * wv.z; acc[2][3] += iv.z * wv.w;
            acc[3][0] += iv.w * wv.x; acc[3][1] += iv.w * wv.y; acc[3][2] += iv.w * wv.z; acc[3][3] += iv.w * wv.w;
        }

        float* part = gPart + kc * (BATCH * OUT_F) + rt * 64;
        #pragma unroll
        for (int bi = 0; bi < 4; bi++) {
            float4 v = make_float4(acc[bi][0], acc[bi][1], acc[bi][2], acc[bi][3]);
            *(float4*)(part + (b4 + bi) * OUT_F + r4) = v;
        }
    }
}

// ---------------------------------------------------------------------------
// K3: reduce 8 k-chunk partials + bias -> out (first 32768 floats), float4
// ---------------------------------------------------------------------------
__global__ void __launch_bounds__(256) k_reduce(const float* __restrict__ bias,
                                                float* __restrict__ outp) {
    const int t    = blockIdx.x * 256 + threadIdx.x;   // < 8192
    const int idx4 = t * 4;
    float4 s = *(const float4*)(bias + (idx4 & 511));
    #pragma unroll
    for (int kc = 0; kc < 8; kc++) {
        const float4 p = *(const float4*)(gPart + kc * (BATCH * OUT_F) + idx4);
        s.x += p.x; s.y += p.y; s.z += p.z; s.w += p.w;
    }
    *(float4*)(outp + idx4) = s;
}

// ---------------------------------------------------------------------------
// inputs: [0] inputs (64x512 f32), [1] grad (64x8x64x64 f32),
//         [2] W (512x512 f32), [3] diag_w (512 f32), [4] bias (512 f32)
// d_out:  out (64x512) followed by jac (64x8x64x64), f32
// ---------------------------------------------------------------------------
extern "C" void kernel_launch(void* const* d_in, const int* in_sizes, int n_in,
                              void* d_out, int out_size) {
    const float* inputs = (const float*)d_in[0];
    const float* grad   = (const float*)d_in[1];
    const float* W      = (const float*)d_in[2];
    const float* diag_w = (const float*)d_in[3];
    const float* bias   = (const float*)d_in[4];
    float* outp = (float*)d_out;

    k_weights<<<64 + 8, 256>>>(W, diag_w, inputs);
    k_main<<<512 + 64, 256>>>(grad, outp);
    k_reduce<<<32, 256>>>(bias, outp);
}